// round 5
// baseline (speedup 1.0000x reference)
#include <cuda_runtime.h>

// Problem dims
#define NCC 4
#define BSZ 16
#define HH  64
#define WW  64
#define OCC 12
#define NTT 32
#define SSLICE (BSZ*HH*WW*OCC)   // 786432 floats per (BS,H,W,OC) slab

// Persistent device state (16B-aligned for float4 access)
__device__ __align__(16) float g_class_h[NCC*SSLICE];
__device__ __align__(16) float g_class_c[NCC*SSLICE];
__device__ __align__(16) float g_genh[2][SSLICE];
__device__ __align__(16) float g_genc[SSLICE];
__device__ __align__(16) float g_hnew[SSLICE];

__device__ __forceinline__ float hsig(float x) {
    return fminf(fmaxf(x + 3.0f, 0.0f), 6.0f) * (1.0f/6.0f);
}

typedef unsigned long long ull;

__device__ __forceinline__ ull pack2(float x) {
    ull r;
    unsigned int xi = __float_as_uint(x);
    asm("mov.b64 %0, {%1, %1};" : "=l"(r) : "r"(xi));
    return r;
}
__device__ __forceinline__ void ffma2(ull& d, ull a, ull b) {
    asm("fma.rn.f32x2 %0, %1, %2, %0;" : "+l"(d) : "l"(a), "l"(b));
}
__device__ __forceinline__ float2 unpack2(ull v) {
    float2 r;
    asm("mov.b64 {%0, %1}, %2;" : "=f"(r.x), "=f"(r.y) : "l"(v));
    return r;
}

// --------------------------------------------------------------------------
__global__ void zero_kernel(float* __restrict__ out)
{
    const int tid    = blockIdx.x * blockDim.x + threadIdx.x;
    const int stride = gridDim.x * blockDim.x;
    for (int i = tid; i < NCC*SSLICE; i += stride) {
        g_class_h[i] = 0.0f;
        g_class_c[i] = 0.0f;
    }
    for (int i = tid; i < SSLICE; i += stride) {
        g_genh[0][i] = 0.0f;
        g_genc[i]    = 0.0f;
        out[i]       = 0.0f;
    }
}

// ==========================================================================
// General cell: 60 in-ch = 5 chunks of 12 (4 class banks flat view + gen_h),
// 48 gate-ch out. grid (8,16)=(row-tile,batch), block 512 = 64 cols x 8
// row-groups; each thread 1 row x 48 oc as 24 f32x2 accumulators.
// 16 warps/CTA -> 4 warps/SMSP for latency hiding.
// ==========================================================================
#define A_SW   (9*60*48)            // 25920 floats
#define A_SIN  (660*13)             // 8580 floats (10 rows x 66 cols, 13 pad)
#define A_SMEM_BYTES ((A_SW + A_SIN + 48)*4)

__global__ __launch_bounds__(512, 1)
void gen_cell_kernel(const float* __restrict__ Wx, const float* __restrict__ Wh,
                     const float* __restrict__ bias, int par)
{
    extern __shared__ float smem[];
    float* sW  = smem;                 // [9][60][48]
    float* sIn = smem + A_SW;          // [660][13]
    float* sB  = smem + A_SW + A_SIN;  // [48] bias

    const int tid = threadIdx.x;
    const int tx  = tid & 63;
    const int rg  = tid >> 6;          // 0..7, owns row y0+rg
    const int b   = blockIdx.y;
    const int y0  = blockIdx.x * 8;

    const float* genh_in  = g_genh[par];
    float*       genh_out = g_genh[par ^ 1];

    // Stage weights: per tap k, Wx block (48x48) then Wh block (12x48)
    for (int k = 0; k < 9; ++k) {
        const float4* sx = (const float4*)(Wx + k*48*48);
        float4*       dx = (float4*)(sW + (k*60)*48);
        for (int e = tid; e < 576; e += 512) dx[e] = sx[e];
        const float4* sh = (const float4*)(Wh + k*12*48);
        float4*       dh = (float4*)(sW + (k*60 + 48)*48);
        if (tid < 144) dh[tid] = sh[tid];
    }
    if (tid < 12) ((float4*)sB)[tid] = ((const float4*)bias)[tid];

    ull acc[24];
    #pragma unroll
    for (int p = 0; p < 24; ++p) acc[p] = 0ull;

    #pragma unroll 1
    for (int ch = 0; ch < 5; ++ch) {
        __syncthreads();
        // Stage 12-ch chunk: 660 px x 3 float4, coalesced LDG.128
        #pragma unroll 1
        for (int e = tid; e < 1980; e += 512) {
            int px = e / 3;
            int q  = e - px*3;
            int yy = px / 66;
            int xx = px - yy*66;
            int gy = y0 + yy - 1;
            int gx = xx - 1;
            float4 v = make_float4(0.f, 0.f, 0.f, 0.f);
            if ((unsigned)gy < 64u && (unsigned)gx < 64u) {
                int pidx = (b*64 + gy)*64 + gx;
                const float* src = (ch < 4)
                    ? g_class_h + (size_t)pidx*48 + ch*12   // raw-reshape view
                    : genh_in   + (size_t)pidx*12;
                v = *(const float4*)(src + q*4);
            }
            float* s = sIn + px*13 + q*4;
            s[0] = v.x; s[1] = v.y; s[2] = v.z; s[3] = v.w;
        }
        __syncthreads();

        #pragma unroll 1
        for (int k = 0; k < 9; ++k) {
            const int ky = k / 3;
            const int kx = k - ky*3;
            const ulonglong2* wb =
                (const ulonglong2*)(sW + (k*60 + ch*12)*48);
            const float* x0 = sIn + ((rg + ky)*66 + tx + kx)*13;
            #pragma unroll 2
            for (int icc = 0; icc < 12; ++icc) {
                ull xp = pack2(x0[icc]);
                const ulonglong2* wp = wb + icc*12;   // 48 floats / channel
                #pragma unroll
                for (int p2 = 0; p2 < 12; ++p2) {
                    ulonglong2 w = wp[p2];
                    ffma2(acc[2*p2],   xp, w.x);
                    ffma2(acc[2*p2+1], xp, w.y);
                }
            }
        }
    }

    // Local LSTM epilogue, vectorized c/h traffic
    {
        float z[48];
        #pragma unroll
        for (int p = 0; p < 24; ++p) {
            float2 v = unpack2(acc[p]);
            z[2*p] = v.x; z[2*p+1] = v.y;
        }
        const int gy  = y0 + rg;
        const int idx = ((b*64 + gy)*64 + tx)*12;
        float4 c4[3], h4[3];
        #pragma unroll
        for (int q = 0; q < 3; ++q) c4[q] = ((const float4*)(g_genc + idx))[q];
        float* cf = (float*)c4;
        float* hf = (float*)h4;
        #pragma unroll
        for (int j = 0; j < 12; ++j) {
            float zi = z[j]      + sB[j];
            float zf = z[12 + j] + sB[12 + j];
            float zg = z[24 + j] + sB[24 + j];
            float zo = z[36 + j] + sB[36 + j];
            float fi = hsig(zi), ff = hsig(zf), fo = hsig(zo);
            float cn = ff * cf[j] + fi * tanhf(zg);
            cf[j] = cn;
            hf[j] = fo * tanhf(cn);
        }
        #pragma unroll
        for (int q = 0; q < 3; ++q) {
            ((float4*)(g_genc + idx))[q]   = c4[q];
            ((float4*)(genh_out + idx))[q] = h4[q];
        }
    }
}

// ==========================================================================
// Class cell: 36 in-ch = 3 chunks of 12 (frame, fresh gen_h, class_h[cid]).
// Epilogue writes h_new to g_hnew and accumulates the output sum directly.
// ==========================================================================
#define B_SW   (9*36*48)            // 15552 floats
#define B_SIN  (660*13)
#define B_SMEM_BYTES ((B_SW + B_SIN + 48)*4)

__global__ __launch_bounds__(512, 1)
void cls_cell_kernel(const float* __restrict__ x, const int* __restrict__ class_ids,
                     const float* __restrict__ Wx, const float* __restrict__ Wh,
                     const float* __restrict__ bias, int t, int par,
                     float* __restrict__ out)
{
    extern __shared__ float smem[];
    float* sW  = smem;
    float* sIn = smem + B_SW;
    float* sB  = smem + B_SW + B_SIN;

    const int tid = threadIdx.x;
    const int tx  = tid & 63;
    const int rg  = tid >> 6;
    const int b   = blockIdx.y;
    const int y0  = blockIdx.x * 8;
    const int cid = __ldg(class_ids + t);

    const float* genh_new = g_genh[par ^ 1];
    const float* chh      = g_class_h + (size_t)cid * SSLICE;
    const float* frame    = x + (size_t)(b*NTT + t)*4096*12;

    for (int k = 0; k < 9; ++k) {
        const float4* sx = (const float4*)(Wx + k*24*48);
        float4*       dx = (float4*)(sW + (k*36)*48);
        for (int e = tid; e < 288; e += 512) dx[e] = sx[e];
        const float4* sh = (const float4*)(Wh + k*12*48);
        float4*       dh = (float4*)(sW + (k*36 + 24)*48);
        if (tid < 144) dh[tid] = sh[tid];
    }
    if (tid < 12) ((float4*)sB)[tid] = ((const float4*)bias)[tid];

    ull acc[24];
    #pragma unroll
    for (int p = 0; p < 24; ++p) acc[p] = 0ull;

    #pragma unroll 1
    for (int ch = 0; ch < 3; ++ch) {
        __syncthreads();
        #pragma unroll 1
        for (int e = tid; e < 1980; e += 512) {
            int px = e / 3;
            int q  = e - px*3;
            int yy = px / 66;
            int xx = px - yy*66;
            int gy = y0 + yy - 1;
            int gx = xx - 1;
            float4 v = make_float4(0.f, 0.f, 0.f, 0.f);
            if ((unsigned)gy < 64u && (unsigned)gx < 64u) {
                int lpix = gy*64 + gx;
                int pidx = b*4096 + lpix;
                const float* src = (ch == 0) ? frame + (size_t)lpix*12
                                 : (ch == 1) ? genh_new + (size_t)pidx*12
                                             : chh + (size_t)pidx*12;
                v = *(const float4*)(src + q*4);
            }
            float* s = sIn + px*13 + q*4;
            s[0] = v.x; s[1] = v.y; s[2] = v.z; s[3] = v.w;
        }
        __syncthreads();

        #pragma unroll 1
        for (int k = 0; k < 9; ++k) {
            const int ky = k / 3;
            const int kx = k - ky*3;
            const ulonglong2* wb =
                (const ulonglong2*)(sW + (k*36 + ch*12)*48);
            const float* x0 = sIn + ((rg + ky)*66 + tx + kx)*13;
            #pragma unroll 2
            for (int icc = 0; icc < 12; ++icc) {
                ull xp = pack2(x0[icc]);
                const ulonglong2* wp = wb + icc*12;   // 48 floats / channel
                #pragma unroll
                for (int p2 = 0; p2 < 12; ++p2) {
                    ulonglong2 w = wp[p2];
                    ffma2(acc[2*p2],   xp, w.x);
                    ffma2(acc[2*p2+1], xp, w.y);
                }
            }
        }
    }

    float* chc = g_class_c + (size_t)cid * SSLICE;

    {
        float z[48];
        #pragma unroll
        for (int p = 0; p < 24; ++p) {
            float2 v = unpack2(acc[p]);
            z[2*p] = v.x; z[2*p+1] = v.y;
        }
        const int gy  = y0 + rg;
        const int idx = ((b*64 + gy)*64 + tx)*12;
        float4 c4[3], h4[3], o4[3];
        #pragma unroll
        for (int q = 0; q < 3; ++q) {
            c4[q] = ((const float4*)(chc + idx))[q];
            o4[q] = ((const float4*)(out + idx))[q];
        }
        float* cf = (float*)c4;
        float* hf = (float*)h4;
        float* of = (float*)o4;
        #pragma unroll
        for (int j = 0; j < 12; ++j) {
            float zi = z[j]      + sB[j];
            float zf = z[12 + j] + sB[12 + j];
            float zg = z[24 + j] + sB[24 + j];
            float zo = z[36 + j] + sB[36 + j];
            float fi = hsig(zi), ff = hsig(zf), fo = hsig(zo);
            float cn = ff * cf[j] + fi * tanhf(zg);
            float hn = fo * tanhf(cn);
            cf[j] = cn;
            hf[j] = hn;
            of[j] += hn;
        }
        #pragma unroll
        for (int q = 0; q < 3; ++q) {
            ((float4*)(chc + idx))[q]    = c4[q];
            ((float4*)(g_hnew + idx))[q] = h4[q];
            ((float4*)(out + idx))[q]    = o4[q];
        }
    }
}

// --------------------------------------------------------------------------
// Copy-only scatter: h_new -> class_h[cid] (out already accumulated in cls).
// --------------------------------------------------------------------------
__global__ void scatter_kernel(const int* __restrict__ class_ids, int t)
{
    const int cid = __ldg(class_ids + t);
    const int i = blockIdx.x * blockDim.x + threadIdx.x;
    if (i < SSLICE/4) {
        reinterpret_cast<float4*>(g_class_h + (size_t)cid*SSLICE)[i] =
            reinterpret_cast<const float4*>(g_hnew)[i];
    }
}

// --------------------------------------------------------------------------
extern "C" void kernel_launch(void* const* d_in, const int* in_sizes, int n_in,
                              void* d_out, int out_size)
{
    const float* x    = (const float*)d_in[0];
    const int*   cids = (const int*)d_in[1];
    const float* Wxg  = (const float*)d_in[2];
    const float* Whg  = (const float*)d_in[3];
    const float* bg   = (const float*)d_in[4];
    const float* Wxc  = (const float*)d_in[5];
    const float* Whc  = (const float*)d_in[6];
    const float* bc   = (const float*)d_in[7];
    float* out = (float*)d_out;

    cudaFuncSetAttribute(gen_cell_kernel, cudaFuncAttributeMaxDynamicSharedMemorySize, A_SMEM_BYTES);
    cudaFuncSetAttribute(cls_cell_kernel, cudaFuncAttributeMaxDynamicSharedMemorySize, B_SMEM_BYTES);

    zero_kernel<<<1024, 256>>>(out);

    for (int t = 0; t < NTT; ++t) {
        const int par = t & 1;
        gen_cell_kernel<<<dim3(8, 16), 512, A_SMEM_BYTES>>>(Wxg, Whg, bg, par);
        cls_cell_kernel<<<dim3(8, 16), 512, B_SMEM_BYTES>>>(x, cids, Wxc, Whc, bc, t, par, out);
        scatter_kernel<<<(SSLICE/4 + 255)/256, 256>>>(cids, t);
    }
}

// round 6
// speedup vs baseline: 1.1549x; 1.1549x over previous
#include <cuda_runtime.h>

// Problem dims
#define NCC 4
#define BSZ 16
#define HH  64
#define WW  64
#define OCC 12
#define NTT 32
#define SSLICE (BSZ*HH*WW*OCC)   // 786432 floats per (BS,H,W,OC) slab

// Persistent device state (16B-aligned for float4 access)
// class_h lives in 5 rotating slabs; schedule below maps logical bank -> slab.
__device__ __align__(16) float g_slabs[5][SSLICE];
__device__ __align__(16) float g_class_c[NCC*SSLICE];
__device__ __align__(16) float g_genh[2][SSLICE];
__device__ __align__(16) float g_genc[SSLICE];

// Slab schedule, computed once per replay by zero_kernel thread 0:
//   g_rslab[t*4+c] = slab holding class_h[c] at the START of step t
//   g_wslab[t]     = slab that step t's cls writes h_new into
__device__ int g_rslab[NTT*NCC];
__device__ int g_wslab[NTT];

__device__ __forceinline__ float hsig(float x) {
    return fminf(fmaxf(x + 3.0f, 0.0f), 6.0f) * (1.0f/6.0f);
}

typedef unsigned long long ull;

__device__ __forceinline__ ull pack2(float x) {
    ull r;
    unsigned int xi = __float_as_uint(x);
    asm("mov.b64 %0, {%1, %1};" : "=l"(r) : "r"(xi));
    return r;
}
__device__ __forceinline__ void ffma2(ull& d, ull a, ull b) {
    asm("fma.rn.f32x2 %0, %1, %2, %0;" : "+l"(d) : "l"(a), "l"(b));
}
__device__ __forceinline__ float2 unpack2(ull v) {
    float2 r;
    asm("mov.b64 {%0, %1}, %2;" : "=f"(r.x), "=f"(r.y) : "l"(v));
    return r;
}

// --------------------------------------------------------------------------
__global__ void zero_kernel(float* __restrict__ out, const int* __restrict__ cids)
{
    const int tid    = blockIdx.x * blockDim.x + threadIdx.x;
    const int stride = gridDim.x * blockDim.x;
    for (int i = tid; i < 5*SSLICE; i += stride)
        (&g_slabs[0][0])[i] = 0.0f;
    for (int i = tid; i < NCC*SSLICE; i += stride)
        g_class_c[i] = 0.0f;
    for (int i = tid; i < SSLICE; i += stride) {
        g_genh[0][i] = 0.0f;
        g_genc[i]    = 0.0f;
        out[i]       = 0.0f;
    }
    if (tid == 0) {
        int slab[NCC] = {0, 1, 2, 3};
        int spare = 4;
        for (int t = 0; t < NTT; ++t) {
            int cid = cids[t];
            #pragma unroll
            for (int c = 0; c < NCC; ++c) g_rslab[t*4 + c] = slab[c];
            g_wslab[t] = spare;
            int old = slab[cid];
            slab[cid] = spare;
            spare = old;
        }
    }
}

// ==========================================================================
// General cell: 60 in-ch = 5 chunks of 12 (4 class banks flat view + gen_h),
// 48 gate-ch out. grid (8,16)=(row-tile,batch), block 256 = 64 cols x 4
// row-groups; each thread 2 rows x 48 oc as 24 f32x2 accumulators per row.
// The flat (BS,H,W,48) reshape view of bank c==b>>2 lives at slab offset
// (pidx&16383)*48 + ch*12.
// ==========================================================================
#define A_SW   (9*60*48)            // 25920 floats
#define A_SIN  (660*13)             // 8580 floats (10 rows x 66 cols, 13 pad)
#define A_SMEM_BYTES ((A_SW + A_SIN + 48)*4)

__global__ __launch_bounds__(256, 1)
void gen_cell_kernel(const float* __restrict__ Wx, const float* __restrict__ Wh,
                     const float* __restrict__ bias, int t, int par)
{
    extern __shared__ float smem[];
    float* sW  = smem;                 // [9][60][48]
    float* sIn = smem + A_SW;          // [660][13]
    float* sB  = smem + A_SW + A_SIN;  // [48] bias

    const int tid = threadIdx.x;
    const int tx  = tid & 63;
    const int rg  = tid >> 6;
    const int b   = blockIdx.y;
    const int y0  = blockIdx.x * 8;
    const float* bankp = g_slabs[g_rslab[t*4 + (b >> 2)]];

    const float* genh_in  = g_genh[par];
    float*       genh_out = g_genh[par ^ 1];

    // Stage weights: per tap k, Wx block (48x48) then Wh block (12x48)
    for (int k = 0; k < 9; ++k) {
        const float4* sx = (const float4*)(Wx + k*48*48);
        float4*       dx = (float4*)(sW + (k*60)*48);
        for (int e = tid; e < 576; e += 256) dx[e] = sx[e];
        const float4* sh = (const float4*)(Wh + k*12*48);
        float4*       dh = (float4*)(sW + (k*60 + 48)*48);
        if (tid < 144) dh[tid] = sh[tid];
    }
    if (tid < 12) ((float4*)sB)[tid] = ((const float4*)bias)[tid];

    ull acc[2][24];
    #pragma unroll
    for (int r = 0; r < 2; ++r)
        #pragma unroll
        for (int p = 0; p < 24; ++p) acc[r][p] = 0ull;

    #pragma unroll 1
    for (int ch = 0; ch < 5; ++ch) {
        __syncthreads();
        // Stage 12-ch chunk: 660 px x 3 float4, coalesced LDG.128
        #pragma unroll 1
        for (int e = tid; e < 1980; e += 256) {
            int px = e / 3;
            int q  = e - px*3;
            int yy = px / 66;
            int xx = px - yy*66;
            int gy = y0 + yy - 1;
            int gx = xx - 1;
            float4 v = make_float4(0.f, 0.f, 0.f, 0.f);
            if ((unsigned)gy < 64u && (unsigned)gx < 64u) {
                int pidx = (b*64 + gy)*64 + gx;
                const float* src = (ch < 4)
                    ? bankp   + (size_t)(pidx & 16383)*48 + ch*12
                    : genh_in + (size_t)pidx*12;
                v = *(const float4*)(src + q*4);
            }
            float* s = sIn + px*13 + q*4;
            s[0] = v.x; s[1] = v.y; s[2] = v.z; s[3] = v.w;
        }
        __syncthreads();

        #pragma unroll 1
        for (int k = 0; k < 9; ++k) {
            const int ky = k / 3;
            const int kx = k - ky*3;
            const ulonglong2* wb =
                (const ulonglong2*)(sW + (k*60 + ch*12)*48);
            const float* x0 = sIn + ((rg*2 + ky)*66 + tx + kx)*13;
            #pragma unroll 2
            for (int icc = 0; icc < 12; ++icc) {
                ull xp0 = pack2(x0[icc]);
                ull xp1 = pack2(x0[66*13 + icc]);
                const ulonglong2* wp = wb + icc*12;   // 48 floats / channel
                #pragma unroll
                for (int p2 = 0; p2 < 12; ++p2) {
                    ulonglong2 w = wp[p2];
                    ffma2(acc[0][2*p2],   xp0, w.x);
                    ffma2(acc[0][2*p2+1], xp0, w.y);
                    ffma2(acc[1][2*p2],   xp1, w.x);
                    ffma2(acc[1][2*p2+1], xp1, w.y);
                }
            }
        }
    }

    // Local LSTM epilogue, vectorized c/h traffic
    #pragma unroll
    for (int r = 0; r < 2; ++r) {
        float z[48];
        #pragma unroll
        for (int p = 0; p < 24; ++p) {
            float2 v = unpack2(acc[r][p]);
            z[2*p] = v.x; z[2*p+1] = v.y;
        }
        const int gy  = y0 + rg*2 + r;
        const int idx = ((b*64 + gy)*64 + tx)*12;
        float4 c4[3], h4[3];
        #pragma unroll
        for (int q = 0; q < 3; ++q) c4[q] = ((const float4*)(g_genc + idx))[q];
        float* cf = (float*)c4;
        float* hf = (float*)h4;
        #pragma unroll
        for (int j = 0; j < 12; ++j) {
            float zi = z[j]      + sB[j];
            float zf = z[12 + j] + sB[12 + j];
            float zg = z[24 + j] + sB[24 + j];
            float zo = z[36 + j] + sB[36 + j];
            float fi = hsig(zi), ff = hsig(zf), fo = hsig(zo);
            float cn = ff * cf[j] + fi * tanhf(zg);
            cf[j] = cn;
            hf[j] = fo * tanhf(cn);
        }
        #pragma unroll
        for (int q = 0; q < 3; ++q) {
            ((float4*)(g_genc + idx))[q]   = c4[q];
            ((float4*)(genh_out + idx))[q] = h4[q];
        }
    }
}

// ==========================================================================
// Class cell: 36 in-ch = 3 chunks of 12 (frame, fresh gen_h, class_h[cid]).
// Reads class_h[cid] from slab rslab[t][cid]; writes h_new into slab
// wslab[t] (no copy); accumulates the output sum directly.
// ==========================================================================
#define B_SW   (9*36*48)            // 15552 floats
#define B_SIN  (660*13)
#define B_SMEM_BYTES ((B_SW + B_SIN + 48)*4)

__global__ __launch_bounds__(256, 1)
void cls_cell_kernel(const float* __restrict__ x, const int* __restrict__ class_ids,
                     const float* __restrict__ Wx, const float* __restrict__ Wh,
                     const float* __restrict__ bias, int t, int par,
                     float* __restrict__ out)
{
    extern __shared__ float smem[];
    float* sW  = smem;
    float* sIn = smem + B_SW;
    float* sB  = smem + B_SW + B_SIN;

    const int tid = threadIdx.x;
    const int tx  = tid & 63;
    const int rg  = tid >> 6;
    const int b   = blockIdx.y;
    const int y0  = blockIdx.x * 8;
    const int cid = __ldg(class_ids + t);

    const float* genh_new = g_genh[par ^ 1];
    const float* chh      = g_slabs[g_rslab[t*4 + cid]];
    float*       hnew     = g_slabs[g_wslab[t]];
    const float* frame    = x + (size_t)(b*NTT + t)*4096*12;

    for (int k = 0; k < 9; ++k) {
        const float4* sx = (const float4*)(Wx + k*24*48);
        float4*       dx = (float4*)(sW + (k*36)*48);
        for (int e = tid; e < 288; e += 256) dx[e] = sx[e];
        const float4* sh = (const float4*)(Wh + k*12*48);
        float4*       dh = (float4*)(sW + (k*36 + 24)*48);
        if (tid < 144) dh[tid] = sh[tid];
    }
    if (tid < 12) ((float4*)sB)[tid] = ((const float4*)bias)[tid];

    ull acc[2][24];
    #pragma unroll
    for (int r = 0; r < 2; ++r)
        #pragma unroll
        for (int p = 0; p < 24; ++p) acc[r][p] = 0ull;

    #pragma unroll 1
    for (int ch = 0; ch < 3; ++ch) {
        __syncthreads();
        #pragma unroll 1
        for (int e = tid; e < 1980; e += 256) {
            int px = e / 3;
            int q  = e - px*3;
            int yy = px / 66;
            int xx = px - yy*66;
            int gy = y0 + yy - 1;
            int gx = xx - 1;
            float4 v = make_float4(0.f, 0.f, 0.f, 0.f);
            if ((unsigned)gy < 64u && (unsigned)gx < 64u) {
                int lpix = gy*64 + gx;
                int pidx = b*4096 + lpix;
                const float* src = (ch == 0) ? frame + (size_t)lpix*12
                                 : (ch == 1) ? genh_new + (size_t)pidx*12
                                             : chh + (size_t)pidx*12;
                v = *(const float4*)(src + q*4);
            }
            float* s = sIn + px*13 + q*4;
            s[0] = v.x; s[1] = v.y; s[2] = v.z; s[3] = v.w;
        }
        __syncthreads();

        #pragma unroll 1
        for (int k = 0; k < 9; ++k) {
            const int ky = k / 3;
            const int kx = k - ky*3;
            const ulonglong2* wb =
                (const ulonglong2*)(sW + (k*36 + ch*12)*48);
            const float* x0 = sIn + ((rg*2 + ky)*66 + tx + kx)*13;
            #pragma unroll 2
            for (int icc = 0; icc < 12; ++icc) {
                ull xp0 = pack2(x0[icc]);
                ull xp1 = pack2(x0[66*13 + icc]);
                const ulonglong2* wp = wb + icc*12;   // 48 floats / channel
                #pragma unroll
                for (int p2 = 0; p2 < 12; ++p2) {
                    ulonglong2 w = wp[p2];
                    ffma2(acc[0][2*p2],   xp0, w.x);
                    ffma2(acc[0][2*p2+1], xp0, w.y);
                    ffma2(acc[1][2*p2],   xp1, w.x);
                    ffma2(acc[1][2*p2+1], xp1, w.y);
                }
            }
        }
    }

    float* chc = g_class_c + (size_t)cid * SSLICE;

    #pragma unroll
    for (int r = 0; r < 2; ++r) {
        float z[48];
        #pragma unroll
        for (int p = 0; p < 24; ++p) {
            float2 v = unpack2(acc[r][p]);
            z[2*p] = v.x; z[2*p+1] = v.y;
        }
        const int gy  = y0 + rg*2 + r;
        const int idx = ((b*64 + gy)*64 + tx)*12;
        float4 c4[3], h4[3], o4[3];
        #pragma unroll
        for (int q = 0; q < 3; ++q) {
            c4[q] = ((const float4*)(chc + idx))[q];
            o4[q] = ((const float4*)(out + idx))[q];
        }
        float* cf = (float*)c4;
        float* hf = (float*)h4;
        float* of = (float*)o4;
        #pragma unroll
        for (int j = 0; j < 12; ++j) {
            float zi = z[j]      + sB[j];
            float zf = z[12 + j] + sB[12 + j];
            float zg = z[24 + j] + sB[24 + j];
            float zo = z[36 + j] + sB[36 + j];
            float fi = hsig(zi), ff = hsig(zf), fo = hsig(zo);
            float cn = ff * cf[j] + fi * tanhf(zg);
            float hn = fo * tanhf(cn);
            cf[j] = cn;
            hf[j] = hn;
            of[j] += hn;
        }
        #pragma unroll
        for (int q = 0; q < 3; ++q) {
            ((float4*)(chc + idx))[q]  = c4[q];
            ((float4*)(hnew + idx))[q] = h4[q];
            ((float4*)(out + idx))[q]  = o4[q];
        }
    }
}

// --------------------------------------------------------------------------
extern "C" void kernel_launch(void* const* d_in, const int* in_sizes, int n_in,
                              void* d_out, int out_size)
{
    const float* x    = (const float*)d_in[0];
    const int*   cids = (const int*)d_in[1];
    const float* Wxg  = (const float*)d_in[2];
    const float* Whg  = (const float*)d_in[3];
    const float* bg   = (const float*)d_in[4];
    const float* Wxc  = (const float*)d_in[5];
    const float* Whc  = (const float*)d_in[6];
    const float* bc   = (const float*)d_in[7];
    float* out = (float*)d_out;

    cudaFuncSetAttribute(gen_cell_kernel, cudaFuncAttributeMaxDynamicSharedMemorySize, A_SMEM_BYTES);
    cudaFuncSetAttribute(cls_cell_kernel, cudaFuncAttributeMaxDynamicSharedMemorySize, B_SMEM_BYTES);

    zero_kernel<<<1024, 256>>>(out, cids);

    for (int t = 0; t < NTT; ++t) {
        const int par = t & 1;
        gen_cell_kernel<<<dim3(8, 16), 256, A_SMEM_BYTES>>>(Wxg, Whg, bg, t, par);
        cls_cell_kernel<<<dim3(8, 16), 256, B_SMEM_BYTES>>>(x, cids, Wxc, Whc, bc, t, par, out);
    }
}

// round 7
// speedup vs baseline: 1.2226x; 1.0587x over previous
#include <cuda_runtime.h>

// Problem dims
#define NCC 4
#define BSZ 16
#define HH  64
#define WW  64
#define OCC 12
#define NTT 32
#define SSLICE (BSZ*HH*WW*OCC)   // 786432 floats per (BS,H,W,OC) slab

// Persistent device state (16B-aligned for float4 access)
// class_h lives in 5 rotating slabs; schedule below maps logical bank -> slab.
__device__ __align__(16) float g_slabs[5][SSLICE];
__device__ __align__(16) float g_class_c[NCC*SSLICE];
__device__ __align__(16) float g_genh[2][SSLICE];
__device__ __align__(16) float g_genc[SSLICE];

// Slab schedule, computed once per replay by zero_kernel thread 0:
//   g_rslab[t*4+c] = slab holding class_h[c] at the START of step t
//   g_wslab[t]     = slab that step t's cls writes h_new into
__device__ int g_rslab[NTT*NCC];
__device__ int g_wslab[NTT];

__device__ __forceinline__ float hsig(float x) {
    return fminf(fmaxf(x + 3.0f, 0.0f), 6.0f) * (1.0f/6.0f);
}

typedef unsigned long long ull;

__device__ __forceinline__ ull pack2(float x) {
    ull r;
    unsigned int xi = __float_as_uint(x);
    asm("mov.b64 %0, {%1, %1};" : "=l"(r) : "r"(xi));
    return r;
}
__device__ __forceinline__ void ffma2(ull& d, ull a, ull b) {
    asm("fma.rn.f32x2 %0, %1, %2, %0;" : "+l"(d) : "l"(a), "l"(b));
}
__device__ __forceinline__ float2 unpack2(ull v) {
    float2 r;
    asm("mov.b64 {%0, %1}, %2;" : "=f"(r.x), "=f"(r.y) : "l"(v));
    return r;
}

// --------------------------------------------------------------------------
__global__ void zero_kernel(float* __restrict__ out, const int* __restrict__ cids)
{
    const int tid    = blockIdx.x * blockDim.x + threadIdx.x;
    const int stride = gridDim.x * blockDim.x;
    for (int i = tid; i < 5*SSLICE; i += stride)
        (&g_slabs[0][0])[i] = 0.0f;
    for (int i = tid; i < NCC*SSLICE; i += stride)
        g_class_c[i] = 0.0f;
    for (int i = tid; i < SSLICE; i += stride) {
        g_genh[0][i] = 0.0f;
        g_genc[i]    = 0.0f;
        out[i]       = 0.0f;
    }
    if (tid == 0) {
        int slab[NCC] = {0, 1, 2, 3};
        int spare = 4;
        for (int t = 0; t < NTT; ++t) {
            int cid = cids[t];
            #pragma unroll
            for (int c = 0; c < NCC; ++c) g_rslab[t*4 + c] = slab[c];
            g_wslab[t] = spare;
            int old = slab[cid];
            slab[cid] = spare;
            spare = old;
        }
    }
}

// ==========================================================================
// General cell: 60 in-ch = 5 chunks of 12 (4 class banks flat view + gen_h),
// 48 gate-ch out. grid (8,16)=(row-tile,batch), block 256 = 64 cols x 4
// row-groups; each thread 2 rows x 48 oc as 24 f32x2 accumulators per row.
// Input tile is CHANNEL-MAJOR [12][660] so x-loads are lane-contiguous
// (1 smem wavefront) instead of 13-line strided.
// ==========================================================================
#define A_SW   (9*60*48)            // 25920 floats
#define A_SIN  (12*660)             // 7920 floats, [icc][10 rows x 66 cols]
#define A_SMEM_BYTES ((A_SW + A_SIN + 48)*4)

__global__ __launch_bounds__(256, 1)
void gen_cell_kernel(const float* __restrict__ Wx, const float* __restrict__ Wh,
                     const float* __restrict__ bias, int t, int par)
{
    extern __shared__ float smem[];
    float* sW  = smem;                 // [9][60][48]
    float* sIn = smem + A_SW;          // [12][660]
    float* sB  = smem + A_SW + A_SIN;  // [48] bias

    const int tid = threadIdx.x;
    const int tx  = tid & 63;
    const int rg  = tid >> 6;
    const int b   = blockIdx.y;
    const int y0  = blockIdx.x * 8;
    const float* bankp = g_slabs[g_rslab[t*4 + (b >> 2)]];

    const float* genh_in  = g_genh[par];
    float*       genh_out = g_genh[par ^ 1];

    // Stage weights: per tap k, Wx block (48x48) then Wh block (12x48)
    for (int k = 0; k < 9; ++k) {
        const float4* sx = (const float4*)(Wx + k*48*48);
        float4*       dx = (float4*)(sW + (k*60)*48);
        for (int e = tid; e < 576; e += 256) dx[e] = sx[e];
        const float4* sh = (const float4*)(Wh + k*12*48);
        float4*       dh = (float4*)(sW + (k*60 + 48)*48);
        if (tid < 144) dh[tid] = sh[tid];
    }
    if (tid < 12) ((float4*)sB)[tid] = ((const float4*)bias)[tid];

    ull acc[2][24];
    #pragma unroll
    for (int r = 0; r < 2; ++r)
        #pragma unroll
        for (int p = 0; p < 24; ++p) acc[r][p] = 0ull;

    #pragma unroll 1
    for (int ch = 0; ch < 5; ++ch) {
        __syncthreads();
        // Stage 12-ch chunk: gmem float4 loads, transpose to [icc][660]
        #pragma unroll 1
        for (int e = tid; e < 1980; e += 256) {
            int px = e / 3;
            int q  = e - px*3;
            int yy = px / 66;
            int xx = px - yy*66;
            int gy = y0 + yy - 1;
            int gx = xx - 1;
            float4 v = make_float4(0.f, 0.f, 0.f, 0.f);
            if ((unsigned)gy < 64u && (unsigned)gx < 64u) {
                int pidx = (b*64 + gy)*64 + gx;
                const float* src = (ch < 4)
                    ? bankp   + (size_t)(pidx & 16383)*48 + ch*12
                    : genh_in + (size_t)pidx*12;
                v = *(const float4*)(src + q*4);
            }
            sIn[(q*4 + 0)*660 + px] = v.x;
            sIn[(q*4 + 1)*660 + px] = v.y;
            sIn[(q*4 + 2)*660 + px] = v.z;
            sIn[(q*4 + 3)*660 + px] = v.w;
        }
        __syncthreads();

        #pragma unroll 1
        for (int k = 0; k < 9; ++k) {
            const int ky = k / 3;
            const int kx = k - ky*3;
            const ulonglong2* wb =
                (const ulonglong2*)(sW + (k*60 + ch*12)*48);
            const float* xbase = sIn + (rg*2 + ky)*66 + tx + kx;
            #pragma unroll 4
            for (int icc = 0; icc < 12; ++icc) {
                ull xp0 = pack2(xbase[icc*660]);
                ull xp1 = pack2(xbase[icc*660 + 66]);
                const ulonglong2* wp = wb + icc*12;   // 48 floats / channel
                #pragma unroll
                for (int p2 = 0; p2 < 12; ++p2) {
                    ulonglong2 w = wp[p2];
                    ffma2(acc[0][2*p2],   xp0, w.x);
                    ffma2(acc[0][2*p2+1], xp0, w.y);
                    ffma2(acc[1][2*p2],   xp1, w.x);
                    ffma2(acc[1][2*p2+1], xp1, w.y);
                }
            }
        }
    }

    // Local LSTM epilogue, vectorized c/h traffic
    #pragma unroll
    for (int r = 0; r < 2; ++r) {
        float z[48];
        #pragma unroll
        for (int p = 0; p < 24; ++p) {
            float2 v = unpack2(acc[r][p]);
            z[2*p] = v.x; z[2*p+1] = v.y;
        }
        const int gy  = y0 + rg*2 + r;
        const int idx = ((b*64 + gy)*64 + tx)*12;
        float4 c4[3], h4[3];
        #pragma unroll
        for (int q = 0; q < 3; ++q) c4[q] = ((const float4*)(g_genc + idx))[q];
        float* cf = (float*)c4;
        float* hf = (float*)h4;
        #pragma unroll
        for (int j = 0; j < 12; ++j) {
            float zi = z[j]      + sB[j];
            float zf = z[12 + j] + sB[12 + j];
            float zg = z[24 + j] + sB[24 + j];
            float zo = z[36 + j] + sB[36 + j];
            float fi = hsig(zi), ff = hsig(zf), fo = hsig(zo);
            float cn = ff * cf[j] + fi * tanhf(zg);
            cf[j] = cn;
            hf[j] = fo * tanhf(cn);
        }
        #pragma unroll
        for (int q = 0; q < 3; ++q) {
            ((float4*)(g_genc + idx))[q]   = c4[q];
            ((float4*)(genh_out + idx))[q] = h4[q];
        }
    }
}

// ==========================================================================
// Class cell: 36 in-ch = 3 chunks of 12 (frame, fresh gen_h, class_h[cid]).
// Reads class_h[cid] from slab rslab[t][cid]; writes h_new into slab
// wslab[t] (no copy); accumulates the output sum directly.
// ==========================================================================
#define B_SW   (9*36*48)            // 15552 floats
#define B_SIN  (12*660)
#define B_SMEM_BYTES ((B_SW + B_SIN + 48)*4)

__global__ __launch_bounds__(256, 1)
void cls_cell_kernel(const float* __restrict__ x, const int* __restrict__ class_ids,
                     const float* __restrict__ Wx, const float* __restrict__ Wh,
                     const float* __restrict__ bias, int t, int par,
                     float* __restrict__ out)
{
    extern __shared__ float smem[];
    float* sW  = smem;
    float* sIn = smem + B_SW;
    float* sB  = smem + B_SW + B_SIN;

    const int tid = threadIdx.x;
    const int tx  = tid & 63;
    const int rg  = tid >> 6;
    const int b   = blockIdx.y;
    const int y0  = blockIdx.x * 8;
    const int cid = __ldg(class_ids + t);

    const float* genh_new = g_genh[par ^ 1];
    const float* chh      = g_slabs[g_rslab[t*4 + cid]];
    float*       hnew     = g_slabs[g_wslab[t]];
    const float* frame    = x + (size_t)(b*NTT + t)*4096*12;

    for (int k = 0; k < 9; ++k) {
        const float4* sx = (const float4*)(Wx + k*24*48);
        float4*       dx = (float4*)(sW + (k*36)*48);
        for (int e = tid; e < 288; e += 256) dx[e] = sx[e];
        const float4* sh = (const float4*)(Wh + k*12*48);
        float4*       dh = (float4*)(sW + (k*36 + 24)*48);
        if (tid < 144) dh[tid] = sh[tid];
    }
    if (tid < 12) ((float4*)sB)[tid] = ((const float4*)bias)[tid];

    ull acc[2][24];
    #pragma unroll
    for (int r = 0; r < 2; ++r)
        #pragma unroll
        for (int p = 0; p < 24; ++p) acc[r][p] = 0ull;

    #pragma unroll 1
    for (int ch = 0; ch < 3; ++ch) {
        __syncthreads();
        #pragma unroll 1
        for (int e = tid; e < 1980; e += 256) {
            int px = e / 3;
            int q  = e - px*3;
            int yy = px / 66;
            int xx = px - yy*66;
            int gy = y0 + yy - 1;
            int gx = xx - 1;
            float4 v = make_float4(0.f, 0.f, 0.f, 0.f);
            if ((unsigned)gy < 64u && (unsigned)gx < 64u) {
                int lpix = gy*64 + gx;
                int pidx = b*4096 + lpix;
                const float* src = (ch == 0) ? frame + (size_t)lpix*12
                                 : (ch == 1) ? genh_new + (size_t)pidx*12
                                             : chh + (size_t)pidx*12;
                v = *(const float4*)(src + q*4);
            }
            sIn[(q*4 + 0)*660 + px] = v.x;
            sIn[(q*4 + 1)*660 + px] = v.y;
            sIn[(q*4 + 2)*660 + px] = v.z;
            sIn[(q*4 + 3)*660 + px] = v.w;
        }
        __syncthreads();

        #pragma unroll 1
        for (int k = 0; k < 9; ++k) {
            const int ky = k / 3;
            const int kx = k - ky*3;
            const ulonglong2* wb =
                (const ulonglong2*)(sW + (k*36 + ch*12)*48);
            const float* xbase = sIn + (rg*2 + ky)*66 + tx + kx;
            #pragma unroll 4
            for (int icc = 0; icc < 12; ++icc) {
                ull xp0 = pack2(xbase[icc*660]);
                ull xp1 = pack2(xbase[icc*660 + 66]);
                const ulonglong2* wp = wb + icc*12;   // 48 floats / channel
                #pragma unroll
                for (int p2 = 0; p2 < 12; ++p2) {
                    ulonglong2 w = wp[p2];
                    ffma2(acc[0][2*p2],   xp0, w.x);
                    ffma2(acc[0][2*p2+1], xp0, w.y);
                    ffma2(acc[1][2*p2],   xp1, w.x);
                    ffma2(acc[1][2*p2+1], xp1, w.y);
                }
            }
        }
    }

    float* chc = g_class_c + (size_t)cid * SSLICE;

    #pragma unroll
    for (int r = 0; r < 2; ++r) {
        float z[48];
        #pragma unroll
        for (int p = 0; p < 24; ++p) {
            float2 v = unpack2(acc[r][p]);
            z[2*p] = v.x; z[2*p+1] = v.y;
        }
        const int gy  = y0 + rg*2 + r;
        const int idx = ((b*64 + gy)*64 + tx)*12;
        float4 c4[3], h4[3], o4[3];
        #pragma unroll
        for (int q = 0; q < 3; ++q) {
            c4[q] = ((const float4*)(chc + idx))[q];
            o4[q] = ((const float4*)(out + idx))[q];
        }
        float* cf = (float*)c4;
        float* hf = (float*)h4;
        float* of = (float*)o4;
        #pragma unroll
        for (int j = 0; j < 12; ++j) {
            float zi = z[j]      + sB[j];
            float zf = z[12 + j] + sB[12 + j];
            float zg = z[24 + j] + sB[24 + j];
            float zo = z[36 + j] + sB[36 + j];
            float fi = hsig(zi), ff = hsig(zf), fo = hsig(zo);
            float cn = ff * cf[j] + fi * tanhf(zg);
            float hn = fo * tanhf(cn);
            cf[j] = cn;
            hf[j] = hn;
            of[j] += hn;
        }
        #pragma unroll
        for (int q = 0; q < 3; ++q) {
            ((float4*)(chc + idx))[q]  = c4[q];
            ((float4*)(hnew + idx))[q] = h4[q];
            ((float4*)(out + idx))[q]  = o4[q];
        }
    }
}

// --------------------------------------------------------------------------
extern "C" void kernel_launch(void* const* d_in, const int* in_sizes, int n_in,
                              void* d_out, int out_size)
{
    const float* x    = (const float*)d_in[0];
    const int*   cids = (const int*)d_in[1];
    const float* Wxg  = (const float*)d_in[2];
    const float* Whg  = (const float*)d_in[3];
    const float* bg   = (const float*)d_in[4];
    const float* Wxc  = (const float*)d_in[5];
    const float* Whc  = (const float*)d_in[6];
    const float* bc   = (const float*)d_in[7];
    float* out = (float*)d_out;

    cudaFuncSetAttribute(gen_cell_kernel, cudaFuncAttributeMaxDynamicSharedMemorySize, A_SMEM_BYTES);
    cudaFuncSetAttribute(cls_cell_kernel, cudaFuncAttributeMaxDynamicSharedMemorySize, B_SMEM_BYTES);

    zero_kernel<<<1024, 256>>>(out, cids);

    for (int t = 0; t < NTT; ++t) {
        const int par = t & 1;
        gen_cell_kernel<<<dim3(8, 16), 256, A_SMEM_BYTES>>>(Wxg, Whg, bg, t, par);
        cls_cell_kernel<<<dim3(8, 16), 256, B_SMEM_BYTES>>>(x, cids, Wxc, Whc, bc, t, par, out);
    }
}